// round 1
// baseline (speedup 1.0000x reference)
#include <cuda_runtime.h>

#define CCH 384
#define HW  56
#define HW2 (HW*HW)
#define KS  21
#define PADR 10
#define TILE 76          // 56 + 2*10 halo
#define NB  32

// Scratch for depthwise output (attn before pointwise). 154 MB static device array.
__device__ float g_attn[(size_t)NB * CCH * HW2];

// ---------------------------------------------------------------------------
// Depthwise 21x21 conv + bias. One block per (n,c) plane.
// blockDim = (56, 4) = 224 threads. Thread (tx, ty) computes column tx,
// output rows [ty*14, ty*14+14). Register-blocked: 14 accumulators, 21
// weights in registers per kernel-column, each shared-mem input value feeds
// up to 14 FMAs.
// ---------------------------------------------------------------------------
__global__ __launch_bounds__(224) void dw_kernel(
    const float* __restrict__ x,
    const float* __restrict__ dw_w,
    const float* __restrict__ dw_b)
{
    const int nc = blockIdx.x;          // n*CCH + c
    const int c  = nc % CCH;
    const float* xp = x + (size_t)nc * HW2;
    float* op = g_attn + (size_t)nc * HW2;

    __shared__ float sh[TILE][TILE];    // 23104 B
    __shared__ float wsh[KS * KS];      // 1764 B

    const int tid = threadIdx.y * 56 + threadIdx.x;

    // load weights for this channel
    for (int i = tid; i < KS * KS; i += 224)
        wsh[i] = dw_w[c * (KS * KS) + i];

    // load haloed input tile (zero padding)
    for (int i = tid; i < TILE * TILE; i += 224) {
        int r  = i / TILE;
        int cc = i - r * TILE;
        int h = r - PADR, w = cc - PADR;
        float v = 0.f;
        if ((unsigned)h < HW && (unsigned)w < HW) v = xp[h * HW + w];
        sh[r][cc] = v;
    }
    __syncthreads();

    const int tx = threadIdx.x;         // output column
    const int r0 = threadIdx.y * 14;    // base output row

    float acc[14];
#pragma unroll
    for (int t = 0; t < 14; t++) acc[t] = 0.f;

    for (int ki = 0; ki < KS; ki++) {   // runtime loop over kernel columns
        float wk[KS];
#pragma unroll
        for (int kj = 0; kj < KS; kj++) wk[kj] = wsh[kj * KS + ki];
#pragma unroll
        for (int r = 0; r < 34; r++) {  // input rows needed by this thread
            float v = sh[r0 + r][tx + ki];
#pragma unroll
            for (int kj = 0; kj < KS; kj++) {
                int t = r - kj;
                if (t >= 0 && t < 14)
                    acc[t] += wk[kj] * v;
            }
        }
    }

    const float b = dw_b[c];
#pragma unroll
    for (int t = 0; t < 14; t++)
        op[(r0 + t) * HW + tx] = acc[t] + b;
}

// ---------------------------------------------------------------------------
// Pointwise 1x1 conv as GEMM: C[co][p] = sum_ci W[co][ci] * attn[n][ci][p],
// fused bias + sigmoid + gating with x.
// Block tile: BM=128 (co) x BN=112 (pixels), BK=8. 256 threads, 8x7 per thread.
// grid = (384/128, 3136/112, 32) = (3, 28, 32)
// ---------------------------------------------------------------------------
#define BM 128
#define BN 112
#define BK 8

__global__ __launch_bounds__(256) void pw_kernel(
    const float* __restrict__ pw_w,
    const float* __restrict__ pw_b,
    const float* __restrict__ x,
    float* __restrict__ out)
{
    const int co0 = blockIdx.x * BM;
    const int p0  = blockIdx.y * BN;
    const int n   = blockIdx.z;

    const float* Bp = g_attn + (size_t)n * CCH * HW2 + p0;   // Bp[ci*HW2 + p]

    __shared__ float As[BK][BM];   // [k][co]
    __shared__ float Bs[BK][BN];   // [k][p]

    const int tid = threadIdx.x;
    const int tm  = tid & 15;      // 16 row groups  -> co micro 8
    const int tn  = tid >> 4;      // 16 col groups  -> p micro 7

    float acc[8][7];
#pragma unroll
    for (int i = 0; i < 8; i++)
#pragma unroll
        for (int j = 0; j < 7; j++) acc[i][j] = 0.f;

    for (int k0 = 0; k0 < CCH; k0 += BK) {
        // A tile: 128x8 = 1024 elems, 4 per thread
#pragma unroll
        for (int i = 0; i < 4; i++) {
            int idx = tid + i * 256;
            int m  = idx >> 3;
            int kk = idx & 7;
            As[kk][m] = pw_w[(size_t)(co0 + m) * CCH + k0 + kk];
        }
        // B tile: 8x112 = 896 elems
        for (int idx = tid; idx < BK * BN; idx += 256) {
            int kk = idx / BN;
            int p  = idx - kk * BN;
            Bs[kk][p] = Bp[(size_t)(k0 + kk) * HW2 + p];
        }
        __syncthreads();

#pragma unroll
        for (int kk = 0; kk < BK; kk++) {
            float a[8], b[7];
#pragma unroll
            for (int i = 0; i < 8; i++) a[i] = As[kk][tm * 8 + i];
#pragma unroll
            for (int j = 0; j < 7; j++) b[j] = Bs[kk][tn * 7 + j];
#pragma unroll
            for (int i = 0; i < 8; i++)
#pragma unroll
                for (int j = 0; j < 7; j++)
                    acc[i][j] += a[i] * b[j];
        }
        __syncthreads();
    }

    // epilogue: bias + sigmoid + gate with x
    const size_t base = (size_t)n * CCH * HW2;
#pragma unroll
    for (int i = 0; i < 8; i++) {
        int co = co0 + tm * 8 + i;
        float bias = pw_b[co];
        size_t rowb = base + (size_t)co * HW2 + p0 + tn * 7;
#pragma unroll
        for (int j = 0; j < 7; j++) {
            float t = acc[i][j] + bias;
            float s = 1.f / (1.f + __expf(-t));
            out[rowb + j] = x[rowb + j] * s;
        }
    }
}

extern "C" void kernel_launch(void* const* d_in, const int* in_sizes, int n_in,
                              void* d_out, int out_size)
{
    const float* x    = (const float*)d_in[0];
    const float* dw_w = (const float*)d_in[1];
    const float* dw_b = (const float*)d_in[2];
    const float* pw_w = (const float*)d_in[3];
    const float* pw_b = (const float*)d_in[4];
    float* out = (float*)d_out;

    dim3 dwBlock(56, 4);
    dw_kernel<<<NB * CCH, dwBlock>>>(x, dw_w, dw_b);

    dim3 pwGrid(CCH / BM, HW2 / BN, NB);
    pw_kernel<<<pwGrid, 256>>>(pw_w, pw_b, x, out);
}

// round 4
// speedup vs baseline: 1.7364x; 1.7364x over previous
#include <cuda_runtime.h>

#define CCH 384
#define HW  56
#define HW2 (HW*HW)
#define KS  21
#define PADR 10
#define TILE 76          // 56 + 2*10 halo
#define NB  32

// Scratch for depthwise output (attn before pointwise). 154 MB static device array.
__device__ float g_attn[(size_t)NB * CCH * HW2];

// ---------------------------------------------------------------------------
// Depthwise 21x21 conv + bias. One block per (n,c) plane. (Identical to the
// R1 version that passed.)
// blockDim = (56, 4) = 224 threads. Thread (tx, ty) computes column tx,
// output rows [ty*14, ty*14+14). Register-blocked: 14 accumulators, 21
// weights in registers per kernel-column, each shared-mem input value feeds
// up to 14 FMAs.
// ---------------------------------------------------------------------------
__global__ __launch_bounds__(224) void dw_kernel(
    const float* __restrict__ x,
    const float* __restrict__ dw_w,
    const float* __restrict__ dw_b)
{
    const int nc = blockIdx.x;          // n*CCH + c
    const int c  = nc % CCH;
    const float* xp = x + (size_t)nc * HW2;
    float* op = g_attn + (size_t)nc * HW2;

    __shared__ float sh[TILE][TILE];    // 23104 B
    __shared__ float wsh[KS * KS];      // 1764 B

    const int tid = threadIdx.y * 56 + threadIdx.x;

    for (int i = tid; i < KS * KS; i += 224)
        wsh[i] = dw_w[c * (KS * KS) + i];

    for (int i = tid; i < TILE * TILE; i += 224) {
        int r  = i / TILE;
        int cc = i - r * TILE;
        int h = r - PADR, w = cc - PADR;
        float v = 0.f;
        if ((unsigned)h < HW && (unsigned)w < HW) v = xp[h * HW + w];
        sh[r][cc] = v;
    }
    __syncthreads();

    const int tx = threadIdx.x;         // output column
    const int r0 = threadIdx.y * 14;    // base output row

    float acc[14];
#pragma unroll
    for (int t = 0; t < 14; t++) acc[t] = 0.f;

    for (int ki = 0; ki < KS; ki++) {   // runtime loop over kernel columns
        float wk[KS];
#pragma unroll
        for (int kj = 0; kj < KS; kj++) wk[kj] = wsh[kj * KS + ki];
#pragma unroll
        for (int r = 0; r < 34; r++) {  // input rows needed by this thread
            float v = sh[r0 + r][tx + ki];
#pragma unroll
            for (int kj = 0; kj < KS; kj++) {
                int t = r - kj;
                if (t >= 0 && t < 14)
                    acc[t] += wk[kj] * v;
            }
        }
    }

    const float b = dw_b[c];
#pragma unroll
    for (int t = 0; t < 14; t++)
        op[(r0 + t) * HW + tx] = acc[t] + b;
}

// ---------------------------------------------------------------------------
// Pointwise 1x1 conv as GEMM: C[co][p] = sum_ci W[co][ci] * attn[n][ci][p],
// fused bias + sigmoid + gating with x.
// BM=128 (co) x BN=112 (p), BK=16, 256 threads, 8x7 micro-tile.
// Software-pipelined: next k-tile prefetched to registers during compute.
// A-fragments read as float4 (ASTRIDE=132 keeps 16B alignment).
// ---------------------------------------------------------------------------
#define BM 128
#define BN 112
#define BK 16
#define ASTRIDE 132
#define NKT (CCH / BK)   // 24

__global__ __launch_bounds__(256) void pw_kernel(
    const float* __restrict__ pw_w,
    const float* __restrict__ pw_b,
    const float* __restrict__ x,
    float* __restrict__ out)
{
    const int co0 = blockIdx.x * BM;
    const int p0  = blockIdx.y * BN;
    const int n   = blockIdx.z;

    const float* Bp = g_attn + (size_t)n * CCH * HW2 + p0;

    __shared__ __align__(16) float As[BK * ASTRIDE];   // As[kk*ASTRIDE + m]
    __shared__ __align__(16) float Bs[BK][BN];

    const int tid = threadIdx.x;
    const int tn  = tid & 15;      // p group: 7 pixels
    const int tm  = tid >> 4;      // co group: 8 channels
    const int m0  = tm * 8;

    const int a_kk = tid & 15;     // A-tile load: k index
    const int a_m  = tid >> 4;     // A-tile load: base co index

    float acc[8][7];
#pragma unroll
    for (int i = 0; i < 8; i++)
#pragma unroll
        for (int j = 0; j < 7; j++) acc[i][j] = 0.f;

    float pa[8], pb[7];

    // prologue: load k-tile 0 into registers
#pragma unroll
    for (int i = 0; i < 8; i++)
        pa[i] = pw_w[(size_t)(co0 + a_m + 16 * i) * CCH + a_kk];
#pragma unroll
    for (int i = 0; i < 7; i++) {
        int idx = tid + i * 256;
        int kk = idx / BN;
        int p  = idx - kk * BN;
        pb[i] = Bp[(size_t)kk * HW2 + p];
    }

    for (int kt = 0; kt < NKT; kt++) {
        // commit prefetched tile to shared
#pragma unroll
        for (int i = 0; i < 8; i++)
            As[a_kk * ASTRIDE + a_m + 16 * i] = pa[i];
#pragma unroll
        for (int i = 0; i < 7; i++) {
            int idx = tid + i * 256;
            int kk = idx / BN;
            int p  = idx - kk * BN;
            Bs[kk][p] = pb[i];
        }
        __syncthreads();

        // prefetch next tile (overlaps with compute below)
        if (kt + 1 < NKT) {
            int k0 = (kt + 1) * BK;
#pragma unroll
            for (int i = 0; i < 8; i++)
                pa[i] = pw_w[(size_t)(co0 + a_m + 16 * i) * CCH + k0 + a_kk];
#pragma unroll
            for (int i = 0; i < 7; i++) {
                int idx = tid + i * 256;
                int kk = idx / BN;
                int p  = idx - kk * BN;
                pb[i] = Bp[(size_t)(k0 + kk) * HW2 + p];
            }
        }

#pragma unroll
        for (int kk = 0; kk < BK; kk++) {
            float4 a0 = *reinterpret_cast<const float4*>(&As[kk * ASTRIDE + m0]);
            float4 a1 = *reinterpret_cast<const float4*>(&As[kk * ASTRIDE + m0 + 4]);
            float a[8] = {a0.x, a0.y, a0.z, a0.w, a1.x, a1.y, a1.z, a1.w};
            float b[7];
#pragma unroll
            for (int j = 0; j < 7; j++) b[j] = Bs[kk][tn * 7 + j];
#pragma unroll
            for (int i = 0; i < 8; i++)
#pragma unroll
                for (int j = 0; j < 7; j++)
                    acc[i][j] += a[i] * b[j];
        }
        __syncthreads();
    }

    // epilogue: bias + sigmoid + gate with x
    const size_t base = (size_t)n * CCH * HW2;
#pragma unroll
    for (int i = 0; i < 8; i++) {
        int co = co0 + m0 + i;
        float bias = pw_b[co];
        size_t rowb = base + (size_t)co * HW2 + p0 + tn * 7;
#pragma unroll
        for (int j = 0; j < 7; j++) {
            float t = acc[i][j] + bias;
            float s = 1.f / (1.f + __expf(-t));
            out[rowb + j] = x[rowb + j] * s;
        }
    }
}

extern "C" void kernel_launch(void* const* d_in, const int* in_sizes, int n_in,
                              void* d_out, int out_size)
{
    const float* x    = (const float*)d_in[0];
    const float* dw_w = (const float*)d_in[1];
    const float* dw_b = (const float*)d_in[2];
    const float* pw_w = (const float*)d_in[3];
    const float* pw_b = (const float*)d_in[4];
    float* out = (float*)d_out;

    dim3 dwBlock(56, 4);
    dw_kernel<<<NB * CCH, dwBlock>>>(x, dw_w, dw_b);

    dim3 pwGrid(CCH / BM, HW2 / BN, NB);
    pw_kernel<<<pwGrid, 256>>>(pw_w, pw_b, x, out);
}